// round 6
// baseline (speedup 1.0000x reference)
#include <cuda_runtime.h>
#include <cstdint>

#define B_    16
#define T_    4096
#define DIM_  256
#define H_    128
#define G3    384
#define BT    65536   // B_*T_
#define CHUNK 128
#define NCHUNK 32     // T_/CHUNK
#define NMT   512     // BT/128 m-tiles
#define NNT   4       // 384/96 n-tiles
#define TICKETS (2*NMT*NNT)  // 4096 per layer

// Scratch: two xg buffers (layer parity), two activation buffers, sync state.
__device__ float g_xg[2][2ull * BT * G3];       // 2 x 201 MB
__device__ float g_buf[2][(size_t)BT * DIM_];   // 2 x 64 MB
__device__ int g_tileflag[3][2][NMT];           // n-tiles done per (l,d,mtile)
__device__ int g_prog[3][2][B_];                // rnn steps done per (l,d,b)
__device__ int g_ticket[3];                     // gemm work queue heads

typedef unsigned long long ull;

__device__ __forceinline__ ull ffma2(ull a, ull b, ull c) {
    ull d;
    asm("fma.rn.f32x2 %0, %1, %2, %3;" : "=l"(d) : "l"(a), "l"(b), "l"(c));
    return d;
}
__device__ __forceinline__ ull fpack2(float lo, float hi) {
    ull r;
    asm("mov.b64 %0, {%1, %2};" : "=l"(r) : "f"(lo), "f"(hi));
    return r;
}
__device__ __forceinline__ float2 funpack(ull v) {
    float2 r;
    asm("mov.b64 {%0, %1}, %2;" : "=f"(r.x), "=f"(r.y) : "l"(v));
    return r;
}
__device__ __forceinline__ float sigmoidf_fast(float x) {
    return __fdividef(1.0f, 1.0f + __expf(-x));
}
__device__ __forceinline__ float tanhf_fast(float x) {
    return __fdividef(2.0f, 1.0f + __expf(-2.0f * x)) - 1.0f;
}

__global__ void init_sync() {
    int i = blockIdx.x * blockDim.x + threadIdx.x;
    if (i < 3 * 2 * NMT) ((int*)g_tileflag)[i] = 0;
    if (i < 3 * 2 * B_) ((int*)g_prog)[i] = 0;
    if (i < 3) g_ticket[i] = 0;
}

// ---------------------------------------------------------------------------
// Fused persistent kernel. Blocks 0..31: recurrence chains (b,d) through all
// 3 layers. Blocks 32..147: gemm workers producing xg tiles from a ticket
// queue, gated on recurrence progress. All 148 CTAs co-resident (occ 1).
// ---------------------------------------------------------------------------
__global__ void __launch_bounds__(384, 1) mega(const float* __restrict__ xin,
                                               const float* __restrict__ Wi,
                                               const float* __restrict__ Wh,
                                               const float* __restrict__ bh,
                                               float* __restrict__ out) {
    const int tid = threadIdx.x;

    if (blockIdx.x < 32) {
        // =================== recurrence CTA: chain (b,d) ===================
        const int b = blockIdx.x & 15;
        const int d = blockIdx.x >> 4;
        const int c0 = tid & 127;
        const int gate = tid >> 7;  // 0=r, 1=z, 2=n
        const bool isN = (gate == 2);

        __shared__ __align__(16) float h_s[H_];
        __shared__ float rr[H_];
        __shared__ float zz[H_];
        const ulonglong2* const hp = (const ulonglong2*)h_s;

        for (int l = 0; l < 3; l++) {
            float* __restrict__ Y = (l == 2) ? out : g_buf[l];
            const float* __restrict__ W = Wh + (size_t)(l * 2 + d) * H_ * G3;
            const float* __restrict__ xgb =
                g_xg[l & 1] + ((size_t)d * BT + (size_t)b * T_) * G3;

            ull w[64];
            {
                const float* Wc = W + tid;
#pragma unroll
                for (int j = 0; j < 64; j++)
                    w[j] = fpack2(Wc[(size_t)(2 * j) * G3],
                                  Wc[(size_t)(2 * j + 1) * G3]);
            }
            const float bias = bh[(size_t)(l * 2 + d) * G3 + tid];
            const float badd = isN ? 0.0f : bias;

            if (tid < H_) h_s[tid] = 0.0f;

            const int sd = d ? -1 : 1;
            const long xstep = (long)sd * G3;
            const long ystep = (long)sd * DIM_;
            const float* xp = xgb + (d ? (size_t)(T_ - 1) * G3 : 0) + tid;
            float* yp = Y + (size_t)b * T_ * DIM_ + d * H_ + c0 +
                        (d ? (size_t)(T_ - 1) * DIM_ : 0);

            // Wait for the first xg chunk, then preload xv (depth-2 pipeline).
            if (tid == 0) {
                int tc0 = d ? (NCHUNK - 1) : 0;
                while (*(volatile int*)&g_tileflag[l][d][b * NCHUNK + tc0] < NNT)
                    __nanosleep(128);
                __threadfence();
            }
            __syncthreads();
            float xv = *xp + badd;
            xp += xstep;
            float xv1 = *xp + badd;
            xp += xstep;

            for (int c = 0; c < NCHUNK; c++) {
                // Wait one chunk ahead (covers the depth-2 prefetch).
                if (tid == 0 && c + 1 < NCHUNK) {
                    int tcn = d ? (NCHUNK - 2 - c) : (c + 1);
                    while (*(volatile int*)&g_tileflag[l][d][b * NCHUNK + tcn] < NNT)
                        __nanosleep(128);
                    __threadfence();
                }
                __syncthreads();

#pragma unroll 1
                for (int t2 = 0; t2 < CHUNK; t2++) {
                    // Issue the t+2 xg load first: ~2 full steps of latency
                    // slack (tolerates loaded-DRAM under worker traffic).
                    float xv2 = *xp + badd;
                    xp += xstep;

                    // Dot: h . Wh[:, tid]; xv pre-folded into the accumulator
                    // for gates r/z (for n it must stay outside r*(...)).
                    ull acc0 = fpack2(isN ? 0.0f : xv, 0.0f);
                    ull acc1 = 0;
#pragma unroll
                    for (int j = 0; j < 32; j++) {
                        ulonglong2 hv = hp[j];
                        acc0 = ffma2(w[2 * j], hv.x, acc0);
                        acc1 = ffma2(w[2 * j + 1], hv.y, acc1);
                    }
                    float2 lo = funpack(acc0), hi = funpack(acc1);
                    float dot = (lo.x + lo.y) + (hi.x + hi.y);

                    float dn = 0.0f;
                    if (gate == 0) {
                        rr[c0] = sigmoidf_fast(dot);
                    } else if (gate == 1) {
                        zz[c0] = sigmoidf_fast(dot);
                    } else {
                        dn = dot + bias;
                    }
                    __syncthreads();  // r,z published

                    if (isN) {
                        float r = rr[c0];
                        float z = zz[c0];
                        float hold = h_s[c0];
                        float n = tanhf_fast(fmaf(r, dn, xv));
                        float hnew = fmaf(z, hold - n, n);
                        h_s[c0] = hnew;
                        *yp = hnew;
                    }
                    __syncthreads();  // new h visible

                    xv = xv1;
                    xv1 = xv2;
                    yp += ystep;
                }

                // Publish progress (release: fence -> bar -> flag).
                __threadfence();
                __syncthreads();
                if (tid == 0) atomicExch(&g_prog[l][d][b], (c + 1) * CHUNK);
            }
            __syncthreads();
        }
    } else {
        // ======================= gemm worker CTA ==========================
        // xg[l][d][bt][c] = sum_k X[bt][k] * Wi[l][d][k][c]
        // BM=128, BN=96, BK=16, 384 threads, 8x4 micro-tile.
        __shared__ __align__(16) float As[16][128];
        __shared__ __align__(16) float Bs[16][96];
        __shared__ int sh_tk;

        const int ar = tid >> 1;             // A fill row (tid<256)
        const int akq = (tid & 1) * 8;       // A fill k-octet
        const int bk = tid / 24;             // B fill k-row 0..15
        const int bc = (tid % 24) * 4;       // B fill col
        const int ry = (tid / 24) * 8;       // micro rows
        const int cx = (tid % 24) * 4;       // micro cols

        for (int l = 0; l < 3; l++) {
            const float* __restrict__ X = (l == 0) ? xin : g_buf[l - 1];
            float* __restrict__ Cb = g_xg[l & 1];

            while (true) {
                if (tid == 0) sh_tk = atomicAdd(&g_ticket[l], 1);
                __syncthreads();
                int tk = sh_tk;
                if (tk >= TICKETS) break;

                // Decode ticket -> (tc, d, b, nt). Layer 0: ends-first tc
                // order (matches rnn consumption); layers 1-2: middle-out
                // (matches readiness).
                int i = tk >> 7;       // 0..31
                int rem = tk & 127;
                int tc;
                if (l == 0) {
                    tc = (i & 1) ? (31 - (i >> 1)) : (i >> 1);
                } else {
                    tc = (i & 1) ? (16 + (i >> 1)) : (15 - (i >> 1));
                }
                int d = rem >> 6;
                int b = (rem >> 2) & 15;
                int nt = rem & 3;
                int m = b * NCHUNK + tc;

                // Gate on upstream recurrence progress (acquire).
                if (l > 0) {
                    if (tid == 0) {
                        int needf = (tc + 1) * CHUNK;
                        int needb = T_ - tc * CHUNK;
                        while (*(volatile int*)&g_prog[l - 1][0][b] < needf)
                            __nanosleep(256);
                        while (*(volatile int*)&g_prog[l - 1][1][b] < needb)
                            __nanosleep(256);
                        __threadfence();
                    }
                    __syncthreads();
                }

                const int m0 = m * 128;
                const int n0 = nt * 96;
                const float* __restrict__ W =
                    Wi + (size_t)(l * 2 + d) * DIM_ * G3;
                float* __restrict__ C = Cb + (size_t)d * BT * G3;

                const float* Ap = X + (size_t)(m0 + ar) * DIM_ + akq;
                const float* Bp = W + (size_t)bk * G3 + n0 + bc;

                float acc[8][4];
#pragma unroll
                for (int ii = 0; ii < 8; ii++)
#pragma unroll
                    for (int jj = 0; jj < 4; jj++) acc[ii][jj] = 0.0f;

                float4 a0, a1, b0;
                if (tid < 256) {
                    a0 = *(const float4*)(Ap);
                    a1 = *(const float4*)(Ap + 4);
                }
                b0 = *(const float4*)(Bp);

#pragma unroll 1
                for (int k0 = 0; k0 < DIM_; k0 += 16) {
                    if (tid < 256) {
                        As[akq + 0][ar] = a0.x; As[akq + 1][ar] = a0.y;
                        As[akq + 2][ar] = a0.z; As[akq + 3][ar] = a0.w;
                        As[akq + 4][ar] = a1.x; As[akq + 5][ar] = a1.y;
                        As[akq + 6][ar] = a1.z; As[akq + 7][ar] = a1.w;
                    }
                    *(float4*)&Bs[bk][bc] = b0;
                    __syncthreads();

                    if (k0 + 16 < DIM_) {
                        if (tid < 256) {
                            a0 = *(const float4*)(Ap + k0 + 16);
                            a1 = *(const float4*)(Ap + k0 + 20);
                        }
                        b0 = *(const float4*)(Bp + (size_t)(k0 + 16) * G3);
                    }

#pragma unroll
                    for (int k = 0; k < 16; k++) {
                        float4 av0 = *(const float4*)&As[k][ry];
                        float4 av1 = *(const float4*)&As[k][ry + 4];
                        float4 bv = *(const float4*)&Bs[k][cx];
                        float a[8] = {av0.x, av0.y, av0.z, av0.w,
                                      av1.x, av1.y, av1.z, av1.w};
                        float bb2[4] = {bv.x, bv.y, bv.z, bv.w};
#pragma unroll
                        for (int ii = 0; ii < 8; ii++)
#pragma unroll
                            for (int jj = 0; jj < 4; jj++)
                                acc[ii][jj] = fmaf(a[ii], bb2[jj], acc[ii][jj]);
                    }
                    __syncthreads();
                }

#pragma unroll
                for (int ii = 0; ii < 8; ii++) {
                    float* crow = C + (size_t)(m0 + ry + ii) * G3 + n0 + cx;
                    *(float4*)crow =
                        make_float4(acc[ii][0], acc[ii][1], acc[ii][2], acc[ii][3]);
                }

                // Publish tile (release).
                __threadfence();
                __syncthreads();
                if (tid == 0) atomicAdd(&g_tileflag[l][d][m], 1);
            }
        }
    }
}

// ---------------------------------------------------------------------------
extern "C" void kernel_launch(void* const* d_in, const int* in_sizes, int n_in,
                              void* d_out, int out_size) {
    (void)in_sizes;
    (void)n_in;
    (void)out_size;
    const float* x = (const float*)d_in[0];    // [16,4096,256]
    const float* Wi = (const float*)d_in[1];   // [3,2,256,384]
    const float* Wh = (const float*)d_in[2];   // [3,2,128,384]
    const float* bh = (const float*)d_in[3];   // [3,2,384]
    float* out = (float*)d_out;                // [16,4096,256]

    init_sync<<<13, 256>>>();
    mega<<<148, 384>>>(x, Wi, Wh, bh, out);
}